// round 2
// baseline (speedup 1.0000x reference)
#include <cuda_runtime.h>

#define N_TOK 32768
#define EMB_D 1024
#define BM 64
#define BN 64
#define BK 16
#define BP 68   // padded B_s row to reduce STS conflicts

// device scratch (no allocations allowed)
__device__ int g_counts[4];
__device__ int g_is64;
__device__ int g_list[4 * N_TOK];  // token slot per bucket entry
__device__ int g_rows[4 * N_TOK];  // embedding-table row per bucket entry

struct Params {
    const float* emb[4];
    const float* W[4];
    int d[4];
};

// Detect whether x is int64 or int32: for int64 ids < 2^31, every odd 32-bit
// word is 0. For int32 random ids in [0, 267734), odd words are ~never all 0.
__global__ void init_kernel(const unsigned int* __restrict__ xw) {
    if (threadIdx.x < 4) g_counts[threadIdx.x] = 0;
    if (threadIdx.x == 0) {
        int is64 = 1;
        for (int i = 0; i < 16; i++)
            if (xw[2 * i + 1] != 0u) { is64 = 0; break; }
        g_is64 = is64;
    }
}

__global__ void classify_kernel(const void* __restrict__ xraw) {
    int i = blockIdx.x * blockDim.x + threadIdx.x;
    if (i >= N_TOK) return;
    int v;
    if (g_is64) v = (int)((const long long*)xraw)[i];
    else        v = ((const int*)xraw)[i];

    int b, lo;
    if (v >= 30000)     { b = 3; lo = 30000; }
    else if (v >= 3000) { b = 2; lo = 3000; }
    else if (v >= 300)  { b = 1; lo = 300; }
    else                { b = 0; lo = 0; }

    int pos = atomicAdd(&g_counts[b], 1);
    g_list[b * N_TOK + pos] = i;
    g_rows[b * N_TOK + pos] = v - lo;
}

__global__ __launch_bounds__(128)
void bucket_gemm_kernel(Params p, float* __restrict__ out) {
    const int b = blockIdx.z;
    const int count = g_counts[b];
    const int row0 = blockIdx.y * BM;
    if (row0 >= count) return;

    const int col0 = blockIdx.x * BN;
    const int d = p.d[b];
    const float* __restrict__ emb = p.emb[b];
    const float* __restrict__ W = p.W[b];

    __shared__ float A_s[BK][BM];
    __shared__ float B_s[BK][BP];
    __shared__ int s_tok[BM];

    const int tid = threadIdx.x;
    const int tx = tid & 15;   // 0..15 -> 4 output cols each
    const int ty = tid >> 4;   // 0..7  -> 8 output rows each

    // --- A-loader state (threads 0..63, one gathered emb row each) ---
    const float* erow = nullptr;
    bool valid = false;
    if (tid < BM) {
        int g = row0 + tid;
        valid = (g < count);
        if (valid) {
            s_tok[tid] = g_list[b * N_TOK + g];
            int r = g_rows[b * N_TOK + g];
            erow = emb + (long long)r * d;
        } else {
            s_tok[tid] = 0;
        }
    }

    // --- B-loader state (threads 64..127) ---
    const int u = tid - BM;          // 0..63
    const int bk = u >> 2;           // 0..15 : k within tile
    const int bc = (u & 3) * 4;      // col base within 16-float strip

    float acc[8][4];
#pragma unroll
    for (int r = 0; r < 8; r++)
#pragma unroll
        for (int c = 0; c < 4; c++) acc[r][c] = 0.0f;

    for (int k0 = 0; k0 < d; k0 += BK) {
        if (tid < BM) {
            float4 v0, v1, v2, v3;
            if (valid) {
                v0 = *(const float4*)(erow + k0);
                v1 = *(const float4*)(erow + k0 + 4);
                v2 = *(const float4*)(erow + k0 + 8);
                v3 = *(const float4*)(erow + k0 + 12);
            } else {
                v0 = make_float4(0.f, 0.f, 0.f, 0.f);
                v1 = v0; v2 = v0; v3 = v0;
            }
            A_s[0][tid] = v0.x;  A_s[1][tid] = v0.y;
            A_s[2][tid] = v0.z;  A_s[3][tid] = v0.w;
            A_s[4][tid] = v1.x;  A_s[5][tid] = v1.y;
            A_s[6][tid] = v1.z;  A_s[7][tid] = v1.w;
            A_s[8][tid] = v2.x;  A_s[9][tid] = v2.y;
            A_s[10][tid] = v2.z; A_s[11][tid] = v2.w;
            A_s[12][tid] = v3.x; A_s[13][tid] = v3.y;
            A_s[14][tid] = v3.z; A_s[15][tid] = v3.w;
        } else {
            const float* wrow = W + (long long)(k0 + bk) * EMB_D + col0 + bc;
            float4 w0 = *(const float4*)(wrow);
            float4 w1 = *(const float4*)(wrow + 16);
            float4 w2 = *(const float4*)(wrow + 32);
            float4 w3 = *(const float4*)(wrow + 48);
            *(float4*)&B_s[bk][bc]      = w0;
            *(float4*)&B_s[bk][bc + 16] = w1;
            *(float4*)&B_s[bk][bc + 32] = w2;
            *(float4*)&B_s[bk][bc + 48] = w3;
        }
        __syncthreads();

#pragma unroll
        for (int k = 0; k < BK; k++) {
            float4 a0 = *(const float4*)&A_s[k][ty * 8];
            float4 a1 = *(const float4*)&A_s[k][ty * 8 + 4];
            float4 bb = *(const float4*)&B_s[k][tx * 4];
            float av[8] = {a0.x, a0.y, a0.z, a0.w, a1.x, a1.y, a1.z, a1.w};
            float bv[4] = {bb.x, bb.y, bb.z, bb.w};
#pragma unroll
            for (int r = 0; r < 8; r++)
#pragma unroll
                for (int c = 0; c < 4; c++)
                    acc[r][c] = fmaf(av[r], bv[c], acc[r][c]);
        }
        __syncthreads();
    }

    // epilogue: scatter rows back to their token slots
#pragma unroll
    for (int r = 0; r < 8; r++) {
        int row = ty * 8 + r;
        if (row0 + row < count) {
            int t = s_tok[row];
            float4 o = make_float4(acc[r][0], acc[r][1], acc[r][2], acc[r][3]);
            *(float4*)&out[(long long)t * EMB_D + col0 + tx * 4] = o;
        }
    }
}

extern "C" void kernel_launch(void* const* d_in, const int* in_sizes, int n_in,
                              void* d_out, int out_size) {
    const void* x = nullptr;
    Params p;
    p.d[0] = 1024; p.d[1] = 512; p.d[2] = 256; p.d[3] = 128;

    for (int i = 0; i < n_in; i++) {
        switch (in_sizes[i]) {
            case 32768:    x        = d_in[i]; break;               // ids (int32 or int64)
            case 307200:   p.emb[0] = (const float*)d_in[i]; break; // 300x1024
            case 1048576:  p.W[0]   = (const float*)d_in[i]; break; // 1024x1024
            case 1382400:  p.emb[1] = (const float*)d_in[i]; break; // 2700x512
            case 524288:   p.W[1]   = (const float*)d_in[i]; break; // 512x1024
            case 6912000:  p.emb[2] = (const float*)d_in[i]; break; // 27000x256
            case 262144:   p.W[2]   = (const float*)d_in[i]; break; // 256x1024
            case 30429952: p.emb[3] = (const float*)d_in[i]; break; // 237734x128
            case 131072:   p.W[3]   = (const float*)d_in[i]; break; // 128x1024
            default: break;
        }
    }

    float* out = (float*)d_out;

    init_kernel<<<1, 32>>>((const unsigned int*)x);
    classify_kernel<<<(N_TOK + 255) / 256, 256>>>(x);

    dim3 grid(EMB_D / BN, (N_TOK + BM - 1) / BM, 4);
    bucket_gemm_kernel<<<grid, 128>>>(p, out);
}

// round 3
// speedup vs baseline: 1.8094x; 1.8094x over previous
#include <cuda_runtime.h>
#include <stdint.h>

#define N_TOK 32768
#define EMB_D 1024
#define BM 128
#define BN 64
#define BK 32
#define A_STR 36   // bank pattern (4m+k)%32 distinct for fragment loads
#define B_STR 72   // bank pattern (8k+n)%32 distinct for fragment loads

// device scratch (no allocations allowed)
__device__ int g_counts[4];
__device__ int g_list[4 * N_TOK];  // token slot per bucket entry
__device__ int g_rows[4 * N_TOK];  // embedding-table row per bucket entry

struct Params {
    const float* emb[4];
    const float* W[4];
    int d[4];
};

__device__ __forceinline__ uint32_t f2tf32(float x) {
    uint32_t u;
    asm("cvt.rna.tf32.f32 %0, %1;" : "=r"(u) : "f"(x));
    return u;
}

// classify: detect int64 vs int32 ids (JAX default x64-off => int32), then
// bucket-compact token indices + embedding rows.
__global__ void classify_kernel(const void* __restrict__ xraw) {
    int i = blockIdx.x * blockDim.x + threadIdx.x;
    if (i >= N_TOK) return;

    // int64 ids < 2^31 have zero odd 32-bit words; int32 random ids do not.
    const unsigned int* xw = (const unsigned int*)xraw;
    unsigned int probe = xw[2 * (threadIdx.x & 15) + 1];
    bool is64 = __all_sync(0xFFFFFFFFu, probe == 0u);

    int v;
    if (is64) v = (int)((const long long*)xraw)[i];
    else      v = ((const int*)xraw)[i];

    int b, lo;
    if (v >= 30000)     { b = 3; lo = 30000; }
    else if (v >= 3000) { b = 2; lo = 3000; }
    else if (v >= 300)  { b = 1; lo = 300; }
    else                { b = 0; lo = 0; }

    int pos = atomicAdd(&g_counts[b], 1);
    g_list[b * N_TOK + pos] = i;
    g_rows[b * N_TOK + pos] = v - lo;
}

__global__ __launch_bounds__(256)
void bucket_gemm_tf32_kernel(Params p, float* __restrict__ out) {
    const int b = blockIdx.z;
    const int count = g_counts[b];
    const int row0 = blockIdx.y * BM;
    if (row0 >= count) return;

    const int col0 = blockIdx.x * BN;
    const int d = p.d[b];
    const float* __restrict__ emb = p.emb[b];
    const float* __restrict__ W = p.W[b];

    __shared__ __align__(16) float A_s[BM][A_STR];
    __shared__ __align__(16) float B_s[BK][B_STR];
    __shared__ int s_tok[BM];

    const int tid = threadIdx.x;
    const int lane = tid & 31;
    const int wid = tid >> 5;
    const int g = lane >> 2;       // groupID 0..7
    const int tig = lane & 3;      // thread-in-group 0..3
    const int warp_m = (wid & 3) * 32;  // 4 warps along M
    const int warp_n = (wid >> 2) * 32; // 2 warps along N

    // --- A staging assignment: 2 threads per row, 16 floats each ---
    const int ar = tid >> 1;            // 0..127
    const int akseg = (tid & 1) * 16;
    const float* erow = nullptr;
    bool avalid = false;
    {
        int grow = row0 + ar;
        avalid = (grow < count);
        if (avalid) {
            if ((tid & 1) == 0) s_tok[ar] = g_list[b * N_TOK + grow];
            int r = g_rows[b * N_TOK + grow];
            erow = emb + (long long)r * d;
        } else if ((tid & 1) == 0) {
            s_tok[ar] = 0;
        }
    }

    float acc[2][4][4];
#pragma unroll
    for (int mt = 0; mt < 2; mt++)
#pragma unroll
        for (int nt = 0; nt < 4; nt++)
#pragma unroll
            for (int c = 0; c < 4; c++) acc[mt][nt][c] = 0.0f;

    for (int k0 = 0; k0 < d; k0 += BK) {
        // stage A tile [BM x BK] (tf32-converted)
#pragma unroll
        for (int j = 0; j < 4; j++) {
            float4 v;
            if (avalid) v = *(const float4*)(erow + k0 + akseg + 4 * j);
            else        v = make_float4(0.f, 0.f, 0.f, 0.f);
            float4 t;
            t.x = __uint_as_float(f2tf32(v.x));
            t.y = __uint_as_float(f2tf32(v.y));
            t.z = __uint_as_float(f2tf32(v.z));
            t.w = __uint_as_float(f2tf32(v.w));
            *(float4*)&A_s[ar][akseg + 4 * j] = t;
        }
        // stage B tile [BK x BN] (tf32-converted): 512 float4, 2 per thread
#pragma unroll
        for (int i = 0; i < 2; i++) {
            int lin = tid + i * 256;
            int brow = lin >> 4;
            int bcol = (lin & 15) * 4;
            float4 v = *(const float4*)(W + (long long)(k0 + brow) * EMB_D + col0 + bcol);
            float4 t;
            t.x = __uint_as_float(f2tf32(v.x));
            t.y = __uint_as_float(f2tf32(v.y));
            t.z = __uint_as_float(f2tf32(v.z));
            t.w = __uint_as_float(f2tf32(v.w));
            *(float4*)&B_s[brow][bcol] = t;
        }
        __syncthreads();

#pragma unroll
        for (int kk = 0; kk < BK; kk += 8) {
            uint32_t a[2][4];
#pragma unroll
            for (int mt = 0; mt < 2; mt++) {
                int m = warp_m + mt * 16;
                a[mt][0] = __float_as_uint(A_s[m + g][kk + tig]);
                a[mt][1] = __float_as_uint(A_s[m + g + 8][kk + tig]);
                a[mt][2] = __float_as_uint(A_s[m + g][kk + tig + 4]);
                a[mt][3] = __float_as_uint(A_s[m + g + 8][kk + tig + 4]);
            }
            uint32_t bf[4][2];
#pragma unroll
            for (int nt = 0; nt < 4; nt++) {
                int n = warp_n + nt * 8;
                bf[nt][0] = __float_as_uint(B_s[kk + tig][n + g]);
                bf[nt][1] = __float_as_uint(B_s[kk + tig + 4][n + g]);
            }
#pragma unroll
            for (int mt = 0; mt < 2; mt++)
#pragma unroll
                for (int nt = 0; nt < 4; nt++) {
                    asm volatile(
                        "mma.sync.aligned.m16n8k8.row.col.f32.tf32.tf32.f32 "
                        "{%0,%1,%2,%3}, {%4,%5,%6,%7}, {%8,%9}, {%0,%1,%2,%3};\n"
                        : "+f"(acc[mt][nt][0]), "+f"(acc[mt][nt][1]),
                          "+f"(acc[mt][nt][2]), "+f"(acc[mt][nt][3])
                        : "r"(a[mt][0]), "r"(a[mt][1]), "r"(a[mt][2]), "r"(a[mt][3]),
                          "r"(bf[nt][0]), "r"(bf[nt][1]));
                }
        }
        __syncthreads();
    }

    // epilogue: scatter rows to token slots
#pragma unroll
    for (int mt = 0; mt < 2; mt++) {
#pragma unroll
        for (int half = 0; half < 2; half++) {
            int lrow = warp_m + mt * 16 + g + half * 8;
            if (row0 + lrow < count) {
                int t = s_tok[lrow];
                float* orow = out + (long long)t * EMB_D + col0 + warp_n;
#pragma unroll
                for (int nt = 0; nt < 4; nt++) {
                    float2 v;
                    v.x = acc[mt][nt][half * 2 + 0];
                    v.y = acc[mt][nt][half * 2 + 1];
                    *(float2*)&orow[nt * 8 + tig * 2] = v;
                }
            }
        }
    }
}

extern "C" void kernel_launch(void* const* d_in, const int* in_sizes, int n_in,
                              void* d_out, int out_size) {
    const void* x = nullptr;
    Params p;
    p.d[0] = 1024; p.d[1] = 512; p.d[2] = 256; p.d[3] = 128;

    for (int i = 0; i < n_in; i++) {
        switch (in_sizes[i]) {
            case 32768:    x        = d_in[i]; break;               // ids
            case 307200:   p.emb[0] = (const float*)d_in[i]; break; // 300x1024
            case 1048576:  p.W[0]   = (const float*)d_in[i]; break; // 1024x1024
            case 1382400:  p.emb[1] = (const float*)d_in[i]; break; // 2700x512
            case 524288:   p.W[1]   = (const float*)d_in[i]; break; // 512x1024
            case 6912000:  p.emb[2] = (const float*)d_in[i]; break; // 27000x256
            case 262144:   p.W[2]   = (const float*)d_in[i]; break; // 256x1024
            case 30429952: p.emb[3] = (const float*)d_in[i]; break; // 237734x128
            case 131072:   p.W[3]   = (const float*)d_in[i]; break; // 128x1024
            default: break;
        }
    }

    float* out = (float*)d_out;

    void* counts_ptr = nullptr;
    cudaGetSymbolAddress(&counts_ptr, g_counts);
    cudaMemsetAsync(counts_ptr, 0, 4 * sizeof(int));

    classify_kernel<<<(N_TOK + 255) / 256, 256>>>(x);

    dim3 grid(EMB_D / BN, (N_TOK + BM - 1) / BM, 4);
    bucket_gemm_tf32_kernel<<<grid, 256>>>(p, out);
}

// round 4
// speedup vs baseline: 2.1048x; 1.1633x over previous
#include <cuda_runtime.h>
#include <stdint.h>

#define N_TOK 32768
#define EMB_D 1024
#define BM 128
#define BN 128
#define BK 32
#define A_STR 36    // fragment LDS banks (4g+tig)%32 distinct
#define B_STR 136   // fragment LDS banks (8*tig+g)%32 distinct

#define SMEM_FLOATS (2 * BM * A_STR + 2 * BK * B_STR + BM)
#define SMEM_BYTES (SMEM_FLOATS * 4)

// device scratch (no allocations allowed)
__device__ int g_counts[4];
__device__ int g_list[4 * N_TOK];  // token slot per bucket entry
__device__ int g_rows[4 * N_TOK];  // embedding-table row per bucket entry

struct Params {
    const float* emb[4];
    const float* W[4];
    int d[4];
};

__device__ __forceinline__ uint32_t f2tf32(float x) {
    uint32_t u;
    asm("cvt.rna.tf32.f32 %0, %1;" : "=r"(u) : "f"(x));
    return u;
}

__device__ __forceinline__ void cp_async16(float* smem_dst, const float* gsrc, bool full) {
    uint32_t s = (uint32_t)__cvta_generic_to_shared(smem_dst);
    int sz = full ? 16 : 0;
    asm volatile("cp.async.cg.shared.global [%0], [%1], 16, %2;\n"
                 :: "r"(s), "l"(gsrc), "r"(sz));
}

// classify: detect int64 vs int32 ids (JAX default x64-off => int32), then
// bucket-compact token indices + embedding rows.
__global__ void classify_kernel(const void* __restrict__ xraw) {
    int i = blockIdx.x * blockDim.x + threadIdx.x;
    if (i >= N_TOK) return;

    const unsigned int* xw = (const unsigned int*)xraw;
    unsigned int probe = xw[2 * (threadIdx.x & 15) + 1];
    bool is64 = __all_sync(0xFFFFFFFFu, probe == 0u);

    int v;
    if (is64) v = (int)((const long long*)xraw)[i];
    else      v = ((const int*)xraw)[i];

    int b, lo;
    if (v >= 30000)     { b = 3; lo = 30000; }
    else if (v >= 3000) { b = 2; lo = 3000; }
    else if (v >= 300)  { b = 1; lo = 300; }
    else                { b = 0; lo = 0; }

    int pos = atomicAdd(&g_counts[b], 1);
    g_list[b * N_TOK + pos] = i;
    g_rows[b * N_TOK + pos] = v - lo;
}

__global__ __launch_bounds__(256, 2)
void bucket_gemm_tf32_kernel(Params p, float* __restrict__ out) {
    const int b = blockIdx.z;
    const int count = g_counts[b];
    const int row0 = blockIdx.y * BM;
    if (row0 >= count) return;

    const int col0 = blockIdx.x * BN;
    const int d = p.d[b];
    const float* __restrict__ emb = p.emb[b];
    const float* __restrict__ W = p.W[b];

    extern __shared__ float smem[];
    float(*A_s)[BM][A_STR] = (float(*)[BM][A_STR])smem;
    float(*B_s)[BK][B_STR] = (float(*)[BK][B_STR])(smem + 2 * BM * A_STR);
    int* s_tok = (int*)(smem + 2 * BM * A_STR + 2 * BK * B_STR);

    const int tid = threadIdx.x;
    const int lane = tid & 31;
    const int wid = tid >> 5;
    const int g = lane >> 2;            // 0..7
    const int tig = lane & 3;           // 0..3
    const int warp_m = (wid & 3) * 32;  // 4 warps along M
    const int warp_n = (wid >> 2) * 64; // 2 warps along N

    // --- A staging: 2 threads per row, 4 x 16B chunks each ---
    const int ar = tid >> 1;
    const int ac0 = (tid & 1) * 16;
    const bool avalid = (row0 + ar) < count;
    const float* erow = emb;
    {
        int gidx = b * N_TOK + row0 + ar;
        if (avalid) {
            if ((tid & 1) == 0) s_tok[ar] = g_list[gidx];
            erow = emb + (long long)g_rows[gidx] * d;
        } else if ((tid & 1) == 0) {
            s_tok[ar] = 0;
        }
    }
    // --- B staging: 8 threads per k-row, 4 x 16B chunks each ---
    const int br = tid >> 3;
    const int bc0 = (tid & 7) * 16;

    float acc[2][8][4];
#pragma unroll
    for (int mt = 0; mt < 2; mt++)
#pragma unroll
        for (int nt = 0; nt < 8; nt++)
#pragma unroll
            for (int c = 0; c < 4; c++) acc[mt][nt][c] = 0.0f;

    const int T = d / BK;

    // prologue: stage tile 0 into buffer 0
    {
#pragma unroll
        for (int j = 0; j < 4; j++)
            cp_async16(&A_s[0][ar][ac0 + 4 * j], erow + ac0 + 4 * j, avalid);
        const float* wrow = W + (long long)br * EMB_D + col0 + bc0;
#pragma unroll
        for (int j = 0; j < 4; j++)
            cp_async16(&B_s[0][br][bc0 + 4 * j], wrow + 4 * j, true);
        asm volatile("cp.async.commit_group;\n" ::: "memory");
    }

    for (int it = 0; it < T; it++) {
        const int cur = it & 1;
        if (it + 1 < T) {
            const int k0n = (it + 1) * BK;
#pragma unroll
            for (int j = 0; j < 4; j++)
                cp_async16(&A_s[cur ^ 1][ar][ac0 + 4 * j],
                           erow + k0n + ac0 + 4 * j, avalid);
            const float* wrow = W + (long long)(k0n + br) * EMB_D + col0 + bc0;
#pragma unroll
            for (int j = 0; j < 4; j++)
                cp_async16(&B_s[cur ^ 1][br][bc0 + 4 * j], wrow + 4 * j, true);
            asm volatile("cp.async.commit_group;\n" ::: "memory");
            asm volatile("cp.async.wait_group 1;\n" ::: "memory");
        } else {
            asm volatile("cp.async.wait_group 0;\n" ::: "memory");
        }
        __syncthreads();

#pragma unroll
        for (int kk = 0; kk < BK; kk += 8) {
            uint32_t a[2][4];
#pragma unroll
            for (int mt = 0; mt < 2; mt++) {
                const int m = warp_m + mt * 16;
                a[mt][0] = f2tf32(A_s[cur][m + g][kk + tig]);
                a[mt][1] = f2tf32(A_s[cur][m + g + 8][kk + tig]);
                a[mt][2] = f2tf32(A_s[cur][m + g][kk + tig + 4]);
                a[mt][3] = f2tf32(A_s[cur][m + g + 8][kk + tig + 4]);
            }
            uint32_t bf[8][2];
#pragma unroll
            for (int nt = 0; nt < 8; nt++) {
                const int n = warp_n + nt * 8;
                bf[nt][0] = f2tf32(B_s[cur][kk + tig][n + g]);
                bf[nt][1] = f2tf32(B_s[cur][kk + tig + 4][n + g]);
            }
#pragma unroll
            for (int mt = 0; mt < 2; mt++)
#pragma unroll
                for (int nt = 0; nt < 8; nt++) {
                    asm volatile(
                        "mma.sync.aligned.m16n8k8.row.col.f32.tf32.tf32.f32 "
                        "{%0,%1,%2,%3}, {%4,%5,%6,%7}, {%8,%9}, {%0,%1,%2,%3};\n"
                        : "+f"(acc[mt][nt][0]), "+f"(acc[mt][nt][1]),
                          "+f"(acc[mt][nt][2]), "+f"(acc[mt][nt][3])
                        : "r"(a[mt][0]), "r"(a[mt][1]), "r"(a[mt][2]), "r"(a[mt][3]),
                          "r"(bf[nt][0]), "r"(bf[nt][1]));
                }
        }
        __syncthreads();
    }

    // epilogue: scatter rows to token slots
#pragma unroll
    for (int mt = 0; mt < 2; mt++) {
#pragma unroll
        for (int half = 0; half < 2; half++) {
            const int lrow = warp_m + mt * 16 + g + half * 8;
            if (row0 + lrow < count) {
                const int t = s_tok[lrow];
                float* orow = out + (long long)t * EMB_D + col0 + warp_n;
#pragma unroll
                for (int nt = 0; nt < 8; nt++) {
                    float2 v;
                    v.x = acc[mt][nt][half * 2 + 0];
                    v.y = acc[mt][nt][half * 2 + 1];
                    *(float2*)&orow[nt * 8 + tig * 2] = v;
                }
            }
        }
    }
}

extern "C" void kernel_launch(void* const* d_in, const int* in_sizes, int n_in,
                              void* d_out, int out_size) {
    const void* x = nullptr;
    Params p;
    p.d[0] = 1024; p.d[1] = 512; p.d[2] = 256; p.d[3] = 128;

    for (int i = 0; i < n_in; i++) {
        switch (in_sizes[i]) {
            case 32768:    x        = d_in[i]; break;               // ids
            case 307200:   p.emb[0] = (const float*)d_in[i]; break; // 300x1024
            case 1048576:  p.W[0]   = (const float*)d_in[i]; break; // 1024x1024
            case 1382400:  p.emb[1] = (const float*)d_in[i]; break; // 2700x512
            case 524288:   p.W[1]   = (const float*)d_in[i]; break; // 512x1024
            case 6912000:  p.emb[2] = (const float*)d_in[i]; break; // 27000x256
            case 262144:   p.W[2]   = (const float*)d_in[i]; break; // 256x1024
            case 30429952: p.emb[3] = (const float*)d_in[i]; break; // 237734x128
            case 131072:   p.W[3]   = (const float*)d_in[i]; break; // 128x1024
            default: break;
        }
    }

    float* out = (float*)d_out;

    cudaFuncSetAttribute(bucket_gemm_tf32_kernel,
                         cudaFuncAttributeMaxDynamicSharedMemorySize, SMEM_BYTES);

    void* counts_ptr = nullptr;
    cudaGetSymbolAddress(&counts_ptr, g_counts);
    cudaMemsetAsync(counts_ptr, 0, 4 * sizeof(int));

    classify_kernel<<<(N_TOK + 255) / 256, 256>>>(x);

    dim3 grid(EMB_D / BN, (N_TOK + BM - 1) / BM, 4);
    bucket_gemm_tf32_kernel<<<grid, 256, SMEM_BYTES>>>(p, out);
}

// round 5
// speedup vs baseline: 2.3638x; 1.1230x over previous
#include <cuda_runtime.h>
#include <cuda_fp16.h>
#include <stdint.h>

#define N_TOK 32768
#define EMB_D 1024
#define BM 128
#define BN 128
#define BK 32
#define A_STR 40    // halves; ldmatrix bank step 20 -> conflict-free
#define B_STR 136   // halves; trans ldmatrix bank step 4 -> conflict-free

// device scratch (no allocations allowed)
__device__ int g_counts[4];
__device__ int g_list[4 * N_TOK];
__device__ int g_rows[4 * N_TOK];

struct Params {
    const float* emb[4];
    const float* W[4];
    int d[4];
};

__device__ __forceinline__ uint32_t pack_h2(float a, float b) {
    __half2 h = __floats2half2_rn(a, b);
    return *(uint32_t*)&h;
}

__device__ __forceinline__ void ldsm_x4(uint32_t* r, uint32_t addr) {
    asm volatile("ldmatrix.sync.aligned.m8n8.x4.shared.b16 {%0,%1,%2,%3}, [%4];"
                 : "=r"(r[0]), "=r"(r[1]), "=r"(r[2]), "=r"(r[3]) : "r"(addr));
}
__device__ __forceinline__ void ldsm_x4_t(uint32_t* r, uint32_t addr) {
    asm volatile("ldmatrix.sync.aligned.m8n8.x4.trans.shared.b16 {%0,%1,%2,%3}, [%4];"
                 : "=r"(r[0]), "=r"(r[1]), "=r"(r[2]), "=r"(r[3]) : "r"(addr));
}

// classify: detect int64 vs int32 ids, bucket-compact tokens + emb rows.
__global__ void classify_kernel(const void* __restrict__ xraw) {
    int i = blockIdx.x * blockDim.x + threadIdx.x;
    if (i >= N_TOK) return;

    const unsigned int* xw = (const unsigned int*)xraw;
    unsigned int probe = xw[2 * (threadIdx.x & 15) + 1];
    bool is64 = __all_sync(0xFFFFFFFFu, probe == 0u);

    int v;
    if (is64) v = (int)((const long long*)xraw)[i];
    else      v = ((const int*)xraw)[i];

    int b, lo;
    if (v >= 30000)     { b = 3; lo = 30000; }
    else if (v >= 3000) { b = 2; lo = 3000; }
    else if (v >= 300)  { b = 1; lo = 300; }
    else                { b = 0; lo = 0; }

    int pos = atomicAdd(&g_counts[b], 1);
    g_list[b * N_TOK + pos] = i;
    g_rows[b * N_TOK + pos] = v - lo;
}

__global__ __launch_bounds__(256, 2)
void bucket_gemm_f16_kernel(Params p, float* __restrict__ out) {
    const int b = blockIdx.z;
    const int count = g_counts[b];
    const int row0 = blockIdx.y * BM;
    if (row0 >= count) return;

    const int col0 = blockIdx.x * BN;
    const int d = p.d[b];
    const float* __restrict__ emb = p.emb[b];
    const float* __restrict__ W = p.W[b];

    __shared__ __align__(16) __half A_s[2][BM][A_STR];
    __shared__ __align__(16) __half B_s[2][BK][B_STR];
    __shared__ int s_tok[BM];

    const int tid = threadIdx.x;
    const int lane = tid & 31;
    const int wid = tid >> 5;
    const int g = lane >> 2;
    const int tig = lane & 3;
    const int warp_m = (wid & 3) * 32;  // 4 warps along M
    const int warp_n = (wid >> 2) * 64; // 2 warps along N

    // --- A staging: 2 threads per row, 16 floats each ---
    const int ar = tid >> 1;
    const int ac0 = (tid & 1) * 16;
    const bool avalid = (row0 + ar) < count;
    const float* erow = emb;
    {
        int gidx = b * N_TOK + row0 + ar;
        if (avalid) {
            if ((tid & 1) == 0) s_tok[ar] = g_list[gidx];
            erow = emb + (long long)g_rows[gidx] * d;
        } else if ((tid & 1) == 0) {
            s_tok[ar] = 0;
        }
    }
    // --- B staging: 8 threads per k-row, 16 floats each ---
    const int br = tid >> 3;
    const int bc0 = (tid & 7) * 16;
    const float* wbase = W + (long long)br * EMB_D + col0 + bc0;

    // ldmatrix base addresses (shared space)
    const uint32_t sA = (uint32_t)__cvta_generic_to_shared(&A_s[0][0][0]);
    const uint32_t sB = (uint32_t)__cvta_generic_to_shared(&B_s[0][0][0]);
    const uint32_t ASZ = BM * A_STR * 2;
    const uint32_t BSZ = BK * B_STR * 2;
    const uint32_t aA0 = sA + ((warp_m + (lane & 15)) * A_STR + (lane >> 4) * 8) * 2;
    const uint32_t aB0 = sB + ((lane & 15) * B_STR + warp_n + (lane >> 4) * 8) * 2;

    float acc[2][8][4];
#pragma unroll
    for (int mt = 0; mt < 2; mt++)
#pragma unroll
        for (int nt = 0; nt < 8; nt++)
#pragma unroll
            for (int c = 0; c < 4; c++) acc[mt][nt][c] = 0.0f;

    const int T = d / BK;
    float4 ra[4], rb[4];

    // --- staging helpers ---
    auto ldg_tile = [&](int k0) {
#pragma unroll
        for (int j = 0; j < 4; j++) {
            if (avalid) ra[j] = *(const float4*)(erow + k0 + ac0 + 4 * j);
            else        ra[j] = make_float4(0.f, 0.f, 0.f, 0.f);
        }
        const float* wr = wbase + (long long)k0 * EMB_D;
#pragma unroll
        for (int j = 0; j < 4; j++)
            rb[j] = *(const float4*)(wr + 4 * j);
    };
    auto sts_tile = [&](int buf) {
        uint4 u0 = make_uint4(pack_h2(ra[0].x, ra[0].y), pack_h2(ra[0].z, ra[0].w),
                              pack_h2(ra[1].x, ra[1].y), pack_h2(ra[1].z, ra[1].w));
        uint4 u1 = make_uint4(pack_h2(ra[2].x, ra[2].y), pack_h2(ra[2].z, ra[2].w),
                              pack_h2(ra[3].x, ra[3].y), pack_h2(ra[3].z, ra[3].w));
        *(uint4*)&A_s[buf][ar][ac0]     = u0;
        *(uint4*)&A_s[buf][ar][ac0 + 8] = u1;
        uint4 v0 = make_uint4(pack_h2(rb[0].x, rb[0].y), pack_h2(rb[0].z, rb[0].w),
                              pack_h2(rb[1].x, rb[1].y), pack_h2(rb[1].z, rb[1].w));
        uint4 v1 = make_uint4(pack_h2(rb[2].x, rb[2].y), pack_h2(rb[2].z, rb[2].w),
                              pack_h2(rb[3].x, rb[3].y), pack_h2(rb[3].z, rb[3].w));
        *(uint4*)&B_s[buf][br][bc0]     = v0;
        *(uint4*)&B_s[buf][br][bc0 + 8] = v1;
    };

    // prologue
    ldg_tile(0);
    sts_tile(0);
    __syncthreads();

    for (int it = 0; it < T; it++) {
        const int cur = it & 1;
        const bool more = (it + 1 < T);
        if (more) ldg_tile((it + 1) * BK);

        const uint32_t aA = aA0 + cur * ASZ;
        const uint32_t aB = aB0 + cur * BSZ;
#pragma unroll
        for (int ks = 0; ks < 2; ks++) {
            const int kk = ks * 16;
            uint32_t a[2][4];
#pragma unroll
            for (int mt = 0; mt < 2; mt++)
                ldsm_x4(a[mt], aA + (mt * 16 * A_STR + kk) * 2);
            uint32_t bf[4][4];
#pragma unroll
            for (int pr = 0; pr < 4; pr++)
                ldsm_x4_t(bf[pr], aB + (kk * B_STR + pr * 16) * 2);
#pragma unroll
            for (int mt = 0; mt < 2; mt++)
#pragma unroll
                for (int nt = 0; nt < 8; nt++) {
                    const uint32_t* bb = &bf[nt >> 1][(nt & 1) * 2];
                    asm volatile(
                        "mma.sync.aligned.m16n8k16.row.col.f32.f16.f16.f32 "
                        "{%0,%1,%2,%3}, {%4,%5,%6,%7}, {%8,%9}, {%0,%1,%2,%3};\n"
                        : "+f"(acc[mt][nt][0]), "+f"(acc[mt][nt][1]),
                          "+f"(acc[mt][nt][2]), "+f"(acc[mt][nt][3])
                        : "r"(a[mt][0]), "r"(a[mt][1]), "r"(a[mt][2]), "r"(a[mt][3]),
                          "r"(bb[0]), "r"(bb[1]));
                }
        }
        __syncthreads();
        if (more) {
            sts_tile(cur ^ 1);
            __syncthreads();
        }
    }

    // epilogue: scatter rows to token slots
#pragma unroll
    for (int mt = 0; mt < 2; mt++) {
#pragma unroll
        for (int half = 0; half < 2; half++) {
            const int lrow = warp_m + mt * 16 + g + half * 8;
            if (row0 + lrow < count) {
                const int t = s_tok[lrow];
                float* orow = out + (long long)t * EMB_D + col0 + warp_n;
#pragma unroll
                for (int nt = 0; nt < 8; nt++) {
                    float2 v;
                    v.x = acc[mt][nt][half * 2 + 0];
                    v.y = acc[mt][nt][half * 2 + 1];
                    *(float2*)&orow[nt * 8 + tig * 2] = v;
                }
            }
        }
    }
}

extern "C" void kernel_launch(void* const* d_in, const int* in_sizes, int n_in,
                              void* d_out, int out_size) {
    const void* x = nullptr;
    Params p;
    p.d[0] = 1024; p.d[1] = 512; p.d[2] = 256; p.d[3] = 128;

    for (int i = 0; i < n_in; i++) {
        switch (in_sizes[i]) {
            case 32768:    x        = d_in[i]; break;
            case 307200:   p.emb[0] = (const float*)d_in[i]; break;
            case 1048576:  p.W[0]   = (const float*)d_in[i]; break;
            case 1382400:  p.emb[1] = (const float*)d_in[i]; break;
            case 524288:   p.W[1]   = (const float*)d_in[i]; break;
            case 6912000:  p.emb[2] = (const float*)d_in[i]; break;
            case 262144:   p.W[2]   = (const float*)d_in[i]; break;
            case 30429952: p.emb[3] = (const float*)d_in[i]; break;
            case 131072:   p.W[3]   = (const float*)d_in[i]; break;
            default: break;
        }
    }

    float* out = (float*)d_out;

    void* counts_ptr = nullptr;
    cudaGetSymbolAddress(&counts_ptr, g_counts);
    cudaMemsetAsync(counts_ptr, 0, 4 * sizeof(int));

    classify_kernel<<<(N_TOK + 255) / 256, 256>>>(x);

    dim3 grid(EMB_D / BN, (N_TOK + BM - 1) / BM, 4);
    bucket_gemm_f16_kernel<<<grid, 256>>>(p, out);
}

// round 6
// speedup vs baseline: 2.3997x; 1.0152x over previous
#include <cuda_runtime.h>
#include <cuda_fp16.h>
#include <stdint.h>

#define N_TOK 32768
#define EMB_D 1024
#define BM 128
#define BN 128
#define BKH 64          // k-tile in halves (128 bytes)

#define A_TILE_B (BM * BKH * 2)       // 16KB
#define B_TILE_B (BKH * BN * 2)       // 16KB
#define SMEM_BYTES (2 * A_TILE_B + 2 * B_TILE_B + BM * 4)

// device scratch (no runtime allocation allowed)
__device__ int g_counts[4];
__device__ int g_list[4 * N_TOK];
__device__ int g_rows[4 * N_TOK];
__device__ __half g_Wh[1966080];            // all W tables, fp16
__device__ __half g_Ah[62914560];           // packed gathered A rows, fp16 (worst case)

__constant__ long long c_abase[4] = {0, 33554432, 50331648, 58720256};
__constant__ long long c_wbase[4] = {0, 1048576, 1572864, 1835008};

struct Params {
    const float* emb[4];
    const float* W[4];
    int d[4];
};

__device__ __forceinline__ uint32_t pack_h2(float a, float b) {
    __half2 h = __floats2half2_rn(a, b);
    return *(uint32_t*)&h;
}

__device__ __forceinline__ void cp16(uint32_t sdst, const __half* gsrc, bool full) {
    int sz = full ? 16 : 0;
    asm volatile("cp.async.cg.shared.global [%0], [%1], 16, %2;\n"
                 :: "r"(sdst), "l"(gsrc), "r"(sz));
}

__device__ __forceinline__ void ldsm_x4(uint32_t* r, uint32_t addr) {
    asm volatile("ldmatrix.sync.aligned.m8n8.x4.shared.b16 {%0,%1,%2,%3}, [%4];"
                 : "=r"(r[0]), "=r"(r[1]), "=r"(r[2]), "=r"(r[3]) : "r"(addr));
}
__device__ __forceinline__ void ldsm_x4_t(uint32_t* r, uint32_t addr) {
    asm volatile("ldmatrix.sync.aligned.m8n8.x4.trans.shared.b16 {%0,%1,%2,%3}, [%4];"
                 : "=r"(r[0]), "=r"(r[1]), "=r"(r[2]), "=r"(r[3]) : "r"(addr));
}

// ---------------- preprocessing ----------------

__global__ void classify_kernel(const void* __restrict__ xraw) {
    int i = blockIdx.x * blockDim.x + threadIdx.x;
    if (i >= N_TOK) return;

    const unsigned int* xw = (const unsigned int*)xraw;
    unsigned int probe = xw[2 * (threadIdx.x & 15) + 1];
    bool is64 = __all_sync(0xFFFFFFFFu, probe == 0u);

    int v;
    if (is64) v = (int)((const long long*)xraw)[i];
    else      v = ((const int*)xraw)[i];

    int b, lo;
    if (v >= 30000)     { b = 3; lo = 30000; }
    else if (v >= 3000) { b = 2; lo = 3000; }
    else if (v >= 300)  { b = 1; lo = 300; }
    else                { b = 0; lo = 0; }

    int pos = atomicAdd(&g_counts[b], 1);
    g_list[b * N_TOK + pos] = i;
    g_rows[b * N_TOK + pos] = v - lo;
}

// convert all W tables to fp16 (1,966,080 floats)
__global__ void convert_w_kernel(Params p) {
    long long i = (long long)(blockIdx.x * blockDim.x + threadIdx.x) * 8;
    int b = (i >= c_wbase[3]) ? 3 : (i >= c_wbase[2]) ? 2 : (i >= c_wbase[1]) ? 1 : 0;
    const float* src = p.W[b] + (i - c_wbase[b]);
    float4 v0 = *(const float4*)(src);
    float4 v1 = *(const float4*)(src + 4);
    uint4 u = make_uint4(pack_h2(v0.x, v0.y), pack_h2(v0.z, v0.w),
                         pack_h2(v1.x, v1.y), pack_h2(v1.z, v1.w));
    *(uint4*)&g_Wh[i] = u;
}

// gather embedding rows per bucket entry, convert to fp16, pack contiguous.
// block: 256 threads = 8 groups of 32; each group handles one bucket entry.
__global__ void gather_a_kernel(Params p) {
    const int b = blockIdx.y;
    const int count = g_counts[b];
    const int e = blockIdx.x * 8 + (threadIdx.x >> 5);
    if (e >= count) return;
    const int lane = threadIdx.x & 31;
    const int d = p.d[b];
    const float* src = p.emb[b] + (long long)g_rows[b * N_TOK + e] * d;
    __half* dst = g_Ah + c_abase[b] + (long long)e * d;
    for (int off = lane * 8; off < d; off += 256) {
        float4 v0 = *(const float4*)(src + off);
        float4 v1 = *(const float4*)(src + off + 4);
        uint4 u = make_uint4(pack_h2(v0.x, v0.y), pack_h2(v0.z, v0.w),
                             pack_h2(v1.x, v1.y), pack_h2(v1.z, v1.w));
        *(uint4*)&dst[off] = u;
    }
}

// ---------------- GEMM ----------------

__global__ __launch_bounds__(256, 2)
void bucket_gemm_f16_kernel(float* __restrict__ out, int d0, int d1, int d2, int d3) {
    const int b = blockIdx.z;
    const int count = g_counts[b];
    const int row0 = blockIdx.y * BM;
    if (row0 >= count) return;

    const int d = (b == 0) ? d0 : (b == 1) ? d1 : (b == 2) ? d2 : d3;
    const int col0 = blockIdx.x * BN;
    const __half* __restrict__ Ab = g_Ah + c_abase[b];
    const __half* __restrict__ Wb = g_Wh + c_wbase[b];

    extern __shared__ __align__(16) char smem[];
    char* A_sm = smem;                       // 2 x 16KB
    char* B_sm = smem + 2 * A_TILE_B;        // 2 x 16KB
    int* s_tok = (int*)(smem + 2 * A_TILE_B + 2 * B_TILE_B);

    const uint32_t sA = (uint32_t)__cvta_generic_to_shared(A_sm);
    const uint32_t sB = (uint32_t)__cvta_generic_to_shared(B_sm);

    const int tid = threadIdx.x;
    const int lane = tid & 31;
    const int wid = tid >> 5;
    const int g = lane >> 2;
    const int tig = lane & 3;
    const int warp_m = (wid & 3) * 32;   // 4 warps along M
    const int warp_n = (wid >> 2) * 64;  // 2 warps along N

    if (tid < BM) {
        s_tok[tid] = (row0 + tid < count) ? g_list[b * N_TOK + row0 + tid] : 0;
    }

    // --- cp.async staging assignments ---
    // A: 128 rows x 8 chunks(16B). 2 threads/row, 4 chunks each.
    const int a_r = tid >> 1;
    const int a_c0 = (tid & 1) * 4;
    const bool a_ok = (row0 + a_r) < count;
    const __half* a_src = Ab + (long long)(row0 + a_r) * d;
    // B: 64 rows x 16 chunks(16B). 4 threads/row, 4 chunks each.
    const int b_r = tid >> 2;
    const int b_c0 = (tid & 3) * 4;
    const __half* b_src = Wb + (long long)b_r * EMB_D + col0;

    auto stage = [&](int it, int buf) {
        uint32_t adst = sA + buf * A_TILE_B + a_r * 128;
        const __half* as = a_src + it * BKH;
#pragma unroll
        for (int j = 0; j < 4; j++) {
            int c = a_c0 + j;
            cp16(adst + ((c ^ (a_r & 7)) << 4), as + c * 8, a_ok);
        }
        uint32_t bdst = sB + buf * B_TILE_B + b_r * 256;
        const __half* bs = b_src + (long long)(it * BKH) * EMB_D;
#pragma unroll
        for (int j = 0; j < 4; j++) {
            int c = b_c0 + j;
            int cs = (c & 8) | ((c & 7) ^ (b_r & 7));
            cp16(bdst + (cs << 4), bs + c * 8, true);
        }
        asm volatile("cp.async.commit_group;\n" ::: "memory");
    };

    float acc[2][8][4];
#pragma unroll
    for (int mt = 0; mt < 2; mt++)
#pragma unroll
        for (int nt = 0; nt < 8; nt++)
#pragma unroll
            for (int c = 0; c < 4; c++) acc[mt][nt][c] = 0.0f;

    const int T = d / BKH;
    stage(0, 0);

    for (int it = 0; it < T; it++) {
        const int cur = it & 1;
        if (it + 1 < T) {
            stage(it + 1, cur ^ 1);
            asm volatile("cp.async.wait_group 1;\n" ::: "memory");
        } else {
            asm volatile("cp.async.wait_group 0;\n" ::: "memory");
        }
        __syncthreads();

        const uint32_t aBase = sA + cur * A_TILE_B;
        const uint32_t bBase = sB + cur * B_TILE_B;
#pragma unroll
        for (int ks = 0; ks < 4; ks++) {
            const int kk = ks * 16;
            uint32_t a[2][4];
#pragma unroll
            for (int mt = 0; mt < 2; mt++) {
                int r = warp_m + mt * 16 + (lane & 15);
                int chunk = (kk >> 3) + (lane >> 4);
                ldsm_x4(a[mt], aBase + r * 128 + ((chunk ^ (r & 7)) << 4));
            }
            uint32_t bf[4][4];
#pragma unroll
            for (int pr = 0; pr < 4; pr++) {
                int kr = kk + (lane & 15);
                int chunk = (warp_n >> 3) + pr * 2 + (lane >> 4);
                int cs = (chunk & 8) | ((chunk & 7) ^ (kr & 7));
                ldsm_x4_t(bf[pr], bBase + kr * 256 + (cs << 4));
            }
#pragma unroll
            for (int mt = 0; mt < 2; mt++)
#pragma unroll
                for (int nt = 0; nt < 8; nt++) {
                    const uint32_t* bb = &bf[nt >> 1][(nt & 1) * 2];
                    asm volatile(
                        "mma.sync.aligned.m16n8k16.row.col.f32.f16.f16.f32 "
                        "{%0,%1,%2,%3}, {%4,%5,%6,%7}, {%8,%9}, {%0,%1,%2,%3};\n"
                        : "+f"(acc[mt][nt][0]), "+f"(acc[mt][nt][1]),
                          "+f"(acc[mt][nt][2]), "+f"(acc[mt][nt][3])
                        : "r"(a[mt][0]), "r"(a[mt][1]), "r"(a[mt][2]), "r"(a[mt][3]),
                          "r"(bb[0]), "r"(bb[1]));
                }
        }
        __syncthreads();
    }

    // epilogue: scatter rows to token slots
#pragma unroll
    for (int mt = 0; mt < 2; mt++) {
#pragma unroll
        for (int half = 0; half < 2; half++) {
            const int lrow = warp_m + mt * 16 + g + half * 8;
            if (row0 + lrow < count) {
                const int t = s_tok[lrow];
                float* orow = out + (long long)t * EMB_D + col0 + warp_n;
#pragma unroll
                for (int nt = 0; nt < 8; nt++) {
                    float2 v;
                    v.x = acc[mt][nt][half * 2 + 0];
                    v.y = acc[mt][nt][half * 2 + 1];
                    *(float2*)&orow[nt * 8 + tig * 2] = v;
                }
            }
        }
    }
}

extern "C" void kernel_launch(void* const* d_in, const int* in_sizes, int n_in,
                              void* d_out, int out_size) {
    const void* x = nullptr;
    Params p;
    p.d[0] = 1024; p.d[1] = 512; p.d[2] = 256; p.d[3] = 128;

    for (int i = 0; i < n_in; i++) {
        switch (in_sizes[i]) {
            case 32768:    x        = d_in[i]; break;
            case 307200:   p.emb[0] = (const float*)d_in[i]; break;
            case 1048576:  p.W[0]   = (const float*)d_in[i]; break;
            case 1382400:  p.emb[1] = (const float*)d_in[i]; break;
            case 524288:   p.W[1]   = (const float*)d_in[i]; break;
            case 6912000:  p.emb[2] = (const float*)d_in[i]; break;
            case 262144:   p.W[2]   = (const float*)d_in[i]; break;
            case 30429952: p.emb[3] = (const float*)d_in[i]; break;
            case 131072:   p.W[3]   = (const float*)d_in[i]; break;
            default: break;
        }
    }

    float* out = (float*)d_out;

    void* counts_ptr = nullptr;
    cudaGetSymbolAddress(&counts_ptr, g_counts);
    cudaMemsetAsync(counts_ptr, 0, 4 * sizeof(int));

    classify_kernel<<<(N_TOK + 255) / 256, 256>>>(x);
    convert_w_kernel<<<1966080 / (256 * 8), 256>>>(p);
    gather_a_kernel<<<dim3(N_TOK / 8, 4), 256>>>(p);

    cudaFuncSetAttribute(bucket_gemm_f16_kernel,
                         cudaFuncAttributeMaxDynamicSharedMemorySize, SMEM_BYTES);
    dim3 grid(EMB_D / BN, (N_TOK + BM - 1) / BM, 4);
    bucket_gemm_f16_kernel<<<grid, 256, SMEM_BYTES>>>(out, 1024, 512, 256, 128);
}

// round 7
// speedup vs baseline: 3.9620x; 1.6510x over previous
#include <cuda_runtime.h>
#include <cuda_fp16.h>
#include <stdint.h>

#define N_TOK 32768
#define EMB_D 1024
#define BM 128
#define BN 128
#define BKH 64          // k-tile in halves (128 bytes)

#define A_TILE_B (BM * BKH * 2)       // 16KB
#define B_TILE_B (BKH * BN * 2)       // 16KB
#define SMEM_BYTES (2 * A_TILE_B + 2 * B_TILE_B + BM * 4)

// device scratch (no runtime allocation allowed)
__device__ int g_counts[4];
__device__ int g_list[4 * N_TOK];
__device__ int g_rows[4 * N_TOK];
__device__ __half g_Wh[1966080];            // all W tables, fp16
__device__ __half g_Ah[62914560];           // packed gathered A rows, fp16 (worst case)

__constant__ long long c_abase[4] = {0, 33554432, 50331648, 58720256};
__constant__ long long c_wbase[4] = {0, 1048576, 1572864, 1835008};

struct Params {
    const float* emb[4];
    const float* W[4];
    int d[4];
};

__device__ __forceinline__ uint32_t pack_h2(float a, float b) {
    __half2 h = __floats2half2_rn(a, b);
    return *(uint32_t*)&h;
}

__device__ __forceinline__ void cp16(uint32_t sdst, const __half* gsrc, bool full) {
    int sz = full ? 16 : 0;
    asm volatile("cp.async.cg.shared.global [%0], [%1], 16, %2;\n"
                 :: "r"(sdst), "l"(gsrc), "r"(sz));
}

__device__ __forceinline__ void ldsm_x4(uint32_t* r, uint32_t addr) {
    asm volatile("ldmatrix.sync.aligned.m8n8.x4.shared.b16 {%0,%1,%2,%3}, [%4];"
                 : "=r"(r[0]), "=r"(r[1]), "=r"(r[2]), "=r"(r[3]) : "r"(addr));
}
__device__ __forceinline__ void ldsm_x4_t(uint32_t* r, uint32_t addr) {
    asm volatile("ldmatrix.sync.aligned.m8n8.x4.trans.shared.b16 {%0,%1,%2,%3}, [%4];"
                 : "=r"(r[0]), "=r"(r[1]), "=r"(r[2]), "=r"(r[3]) : "r"(addr));
}

// ---------------- preprocessing ----------------

// classify with per-block aggregation: 4 global atomics per block instead of
// one per token (within-bucket order is irrelevant).
__global__ void classify_kernel(const void* __restrict__ xraw) {
    __shared__ int s_cnt[4];
    __shared__ int s_base[4];
    const int tid = threadIdx.x;
    const int i = blockIdx.x * 256 + tid;
    if (tid < 4) s_cnt[tid] = 0;
    __syncthreads();

    const unsigned int* xw = (const unsigned int*)xraw;
    unsigned int probe = xw[2 * (tid & 15) + 1];
    bool is64 = __all_sync(0xFFFFFFFFu, probe == 0u);

    int v;
    if (is64) v = (int)((const long long*)xraw)[i];
    else      v = ((const int*)xraw)[i];

    int b, lo;
    if (v >= 30000)     { b = 3; lo = 30000; }
    else if (v >= 3000) { b = 2; lo = 3000; }
    else if (v >= 300)  { b = 1; lo = 300; }
    else                { b = 0; lo = 0; }

    int local = atomicAdd(&s_cnt[b], 1);
    __syncthreads();
    if (tid < 4) s_base[tid] = atomicAdd(&g_counts[tid], s_cnt[tid]);
    __syncthreads();

    int pos = s_base[b] + local;
    g_list[b * N_TOK + pos] = i;
    g_rows[b * N_TOK + pos] = v - lo;
}

// Fused gather (buckets 0-3) + W conversion (y==4).
// Gather: thread <-> one 8-float chunk; 16 consecutive threads stream one row
// (d=128) -> fully coalesced 32B sectors, all lanes active, grid-stride MLP.
__global__ void prep_kernel(Params p) {
    const int y = blockIdx.y;
    const int t0 = blockIdx.x * 256 + threadIdx.x;
    const int stride = gridDim.x * 256;

    if (y == 4) {
        for (int idx = t0; idx < 1966080 / 8; idx += stride) {
            long long i = (long long)idx * 8;
            int b = (i >= c_wbase[3]) ? 3 : (i >= c_wbase[2]) ? 2 :
                    (i >= c_wbase[1]) ? 1 : 0;
            const float* src = p.W[b] + (i - c_wbase[b]);
            float4 v0 = *(const float4*)(src);
            float4 v1 = *(const float4*)(src + 4);
            uint4 u = make_uint4(pack_h2(v0.x, v0.y), pack_h2(v0.z, v0.w),
                                 pack_h2(v1.x, v1.y), pack_h2(v1.z, v1.w));
            *(uint4*)&g_Wh[i] = u;
        }
        return;
    }

    const int b = y;
    const int d = p.d[b];
    const int lg = (d == 1024) ? 7 : (d == 512) ? 6 : (d == 256) ? 5 : 4; // log2(d/8)
    const int cmask = (1 << lg) - 1;
    const int total = g_counts[b] << lg;
    const float* __restrict__ emb = p.emb[b];
    __half* __restrict__ dst0 = g_Ah + c_abase[b];
    const int* __restrict__ rows = g_rows + b * N_TOK;

    for (int idx = t0; idx < total; idx += stride) {
        int e = idx >> lg;
        int c = (idx & cmask) * 8;
        const float* src = emb + (long long)rows[e] * d + c;
        float4 v0 = *(const float4*)(src);
        float4 v1 = *(const float4*)(src + 4);
        uint4 u = make_uint4(pack_h2(v0.x, v0.y), pack_h2(v0.z, v0.w),
                             pack_h2(v1.x, v1.y), pack_h2(v1.z, v1.w));
        *(uint4*)&dst0[(long long)e * d + c] = u;
    }
}

// ---------------- GEMM (unchanged from R6) ----------------

__global__ __launch_bounds__(256, 2)
void bucket_gemm_f16_kernel(float* __restrict__ out, int d0, int d1, int d2, int d3) {
    const int b = blockIdx.z;
    const int count = g_counts[b];
    const int row0 = blockIdx.y * BM;
    if (row0 >= count) return;

    const int d = (b == 0) ? d0 : (b == 1) ? d1 : (b == 2) ? d2 : d3;
    const int col0 = blockIdx.x * BN;
    const __half* __restrict__ Ab = g_Ah + c_abase[b];
    const __half* __restrict__ Wb = g_Wh + c_wbase[b];

    extern __shared__ __align__(16) char smem[];
    char* A_sm = smem;
    char* B_sm = smem + 2 * A_TILE_B;
    int* s_tok = (int*)(smem + 2 * A_TILE_B + 2 * B_TILE_B);

    const uint32_t sA = (uint32_t)__cvta_generic_to_shared(A_sm);
    const uint32_t sB = (uint32_t)__cvta_generic_to_shared(B_sm);

    const int tid = threadIdx.x;
    const int lane = tid & 31;
    const int wid = tid >> 5;
    const int g = lane >> 2;
    const int tig = lane & 3;
    const int warp_m = (wid & 3) * 32;
    const int warp_n = (wid >> 2) * 64;

    if (tid < BM) {
        s_tok[tid] = (row0 + tid < count) ? g_list[b * N_TOK + row0 + tid] : 0;
    }

    const int a_r = tid >> 1;
    const int a_c0 = (tid & 1) * 4;
    const bool a_ok = (row0 + a_r) < count;
    const __half* a_src = Ab + (long long)(row0 + a_r) * d;
    const int b_r = tid >> 2;
    const int b_c0 = (tid & 3) * 4;
    const __half* b_src = Wb + (long long)b_r * EMB_D + col0;

    auto stage = [&](int it, int buf) {
        uint32_t adst = sA + buf * A_TILE_B + a_r * 128;
        const __half* as = a_src + it * BKH;
#pragma unroll
        for (int j = 0; j < 4; j++) {
            int c = a_c0 + j;
            cp16(adst + ((c ^ (a_r & 7)) << 4), as + c * 8, a_ok);
        }
        uint32_t bdst = sB + buf * B_TILE_B + b_r * 256;
        const __half* bs = b_src + (long long)(it * BKH) * EMB_D;
#pragma unroll
        for (int j = 0; j < 4; j++) {
            int c = b_c0 + j;
            int cs = (c & 8) | ((c & 7) ^ (b_r & 7));
            cp16(bdst + (cs << 4), bs + c * 8, true);
        }
        asm volatile("cp.async.commit_group;\n" ::: "memory");
    };

    float acc[2][8][4];
#pragma unroll
    for (int mt = 0; mt < 2; mt++)
#pragma unroll
        for (int nt = 0; nt < 8; nt++)
#pragma unroll
            for (int c = 0; c < 4; c++) acc[mt][nt][c] = 0.0f;

    const int T = d / BKH;
    stage(0, 0);

    for (int it = 0; it < T; it++) {
        const int cur = it & 1;
        if (it + 1 < T) {
            stage(it + 1, cur ^ 1);
            asm volatile("cp.async.wait_group 1;\n" ::: "memory");
        } else {
            asm volatile("cp.async.wait_group 0;\n" ::: "memory");
        }
        __syncthreads();

        const uint32_t aBase = sA + cur * A_TILE_B;
        const uint32_t bBase = sB + cur * B_TILE_B;
#pragma unroll
        for (int ks = 0; ks < 4; ks++) {
            const int kk = ks * 16;
            uint32_t a[2][4];
#pragma unroll
            for (int mt = 0; mt < 2; mt++) {
                int r = warp_m + mt * 16 + (lane & 15);
                int chunk = (kk >> 3) + (lane >> 4);
                ldsm_x4(a[mt], aBase + r * 128 + ((chunk ^ (r & 7)) << 4));
            }
            uint32_t bf[4][4];
#pragma unroll
            for (int pr = 0; pr < 4; pr++) {
                int kr = kk + (lane & 15);
                int chunk = (warp_n >> 3) + pr * 2 + (lane >> 4);
                int cs = (chunk & 8) | ((chunk & 7) ^ (kr & 7));
                ldsm_x4_t(bf[pr], bBase + kr * 256 + (cs << 4));
            }
#pragma unroll
            for (int mt = 0; mt < 2; mt++)
#pragma unroll
                for (int nt = 0; nt < 8; nt++) {
                    const uint32_t* bb = &bf[nt >> 1][(nt & 1) * 2];
                    asm volatile(
                        "mma.sync.aligned.m16n8k16.row.col.f32.f16.f16.f32 "
                        "{%0,%1,%2,%3}, {%4,%5,%6,%7}, {%8,%9}, {%0,%1,%2,%3};\n"
                        : "+f"(acc[mt][nt][0]), "+f"(acc[mt][nt][1]),
                          "+f"(acc[mt][nt][2]), "+f"(acc[mt][nt][3])
                        : "r"(a[mt][0]), "r"(a[mt][1]), "r"(a[mt][2]), "r"(a[mt][3]),
                          "r"(bb[0]), "r"(bb[1]));
                }
        }
        __syncthreads();
    }

#pragma unroll
    for (int mt = 0; mt < 2; mt++) {
#pragma unroll
        for (int half = 0; half < 2; half++) {
            const int lrow = warp_m + mt * 16 + g + half * 8;
            if (row0 + lrow < count) {
                const int t = s_tok[lrow];
                float* orow = out + (long long)t * EMB_D + col0 + warp_n;
#pragma unroll
                for (int nt = 0; nt < 8; nt++) {
                    float2 v;
                    v.x = acc[mt][nt][half * 2 + 0];
                    v.y = acc[mt][nt][half * 2 + 1];
                    *(float2*)&orow[nt * 8 + tig * 2] = v;
                }
            }
        }
    }
}

extern "C" void kernel_launch(void* const* d_in, const int* in_sizes, int n_in,
                              void* d_out, int out_size) {
    const void* x = nullptr;
    Params p;
    p.d[0] = 1024; p.d[1] = 512; p.d[2] = 256; p.d[3] = 128;

    for (int i = 0; i < n_in; i++) {
        switch (in_sizes[i]) {
            case 32768:    x        = d_in[i]; break;
            case 307200:   p.emb[0] = (const float*)d_in[i]; break;
            case 1048576:  p.W[0]   = (const float*)d_in[i]; break;
            case 1382400:  p.emb[1] = (const float*)d_in[i]; break;
            case 524288:   p.W[1]   = (const float*)d_in[i]; break;
            case 6912000:  p.emb[2] = (const float*)d_in[i]; break;
            case 262144:   p.W[2]   = (const float*)d_in[i]; break;
            case 30429952: p.emb[3] = (const float*)d_in[i]; break;
            case 131072:   p.W[3]   = (const float*)d_in[i]; break;
            default: break;
        }
    }

    float* out = (float*)d_out;

    void* counts_ptr = nullptr;
    cudaGetSymbolAddress(&counts_ptr, g_counts);
    cudaMemsetAsync(counts_ptr, 0, 4 * sizeof(int));

    classify_kernel<<<N_TOK / 256, 256>>>(x);
    prep_kernel<<<dim3(384, 5), 256>>>(p);

    cudaFuncSetAttribute(bucket_gemm_f16_kernel,
                         cudaFuncAttributeMaxDynamicSharedMemorySize, SMEM_BYTES);
    dim3 grid(EMB_D / BN, (N_TOK + BM - 1) / BM, 4);
    bucket_gemm_f16_kernel<<<grid, 256, SMEM_BYTES>>>(out, 1024, 512, 256, 128);
}